// round 15
// baseline (speedup 1.0000x reference)
#include <cuda_runtime.h>
#include <cstdint>

// LayerNormSoftmaxChain: x[N,4] -> LN(4) -> @W[4,3] -> softmax(3) -> out[N,3]
// N = 8388608. HBM-streaming: 16B in / 12B out per row (224 MiB total).
//
// R15: kill the two warp-idling structures left in R14.
//  - PARALLEL fold: warp 0's 32 lanes compute the param fold cooperatively
//    (lane handles W-row l&3, width-4 butterfly shuffles) -> prologue is one
//    parallel load latency, not a serial 20-load chain.
//  - PER-WARP staging: warp w owns rows w*128..w*128+127. Loads stay
//    warp-coalesced (512B/request); outputs staged in a private 1536B smem
//    region and flushed after only __syncwarp(). No block-wide staging
//    barrier -> warps decoupled. Only one __syncthreads (fold) remains.
//  - params re-read per iteration as 2 volatile LDS.128 (not hoistable ->
//    regs stay ~32 -> 8 blocks/SM), E0/E1 hoisted in 2 regs.
//
// Algebra (rel_err ~2e-7 verified since R6):
//   B[i][j] = gamma[i]*(W[i][j+1]-W[i][0]) ; B' = B - colmean(B)
//   d_j = x . B'_j ; e_j = E_j*exp(inv*d_j), E_j = exp(sum_i beta_i*(W_ij+1-W_i0))
//   out = {1, e0, e1} / (1 + e0 + e1)

#define ROWS_PER_BLOCK 1024   // 256 threads * 4 rows

__device__ __forceinline__ float4 lds128_volatile(uint32_t saddr) {
    float4 r;
    asm volatile("ld.volatile.shared.v4.f32 {%0, %1, %2, %3}, [%4];"
                 : "=f"(r.x), "=f"(r.y), "=f"(r.z), "=f"(r.w)
                 : "r"(saddr));
    return r;
}

__global__ __launch_bounds__(256, 7)
void lnsm_kernel(const float4* __restrict__ x4,
                 const float* __restrict__ W,
                 const float* __restrict__ gamma,
                 const float* __restrict__ beta,
                 float4* __restrict__ out4)
{
    __shared__ __align__(16) float s[ROWS_PER_BLOCK * 3];  // 12 KB, per-warp regions
    __shared__ __align__(16) float sp[12];                 // B0[4], B1[4], E0, E1

    const int t = threadIdx.x;
    const int w = t >> 5;
    const int l = t & 31;

    const float4* xb = x4 + (size_t)blockIdx.x * ROWS_PER_BLOCK + w * 128;

    // Front-batch 4 coalesced LDG.128 (MLP=4): warp w covers rows
    // w*128 + r*32 + lane -> each request is contiguous 512B.
    float4 vs[4];
    vs[0] = xb[l];
    vs[1] = xb[l + 32];
    vs[2] = xb[l + 64];
    vs[3] = xb[l + 96];

    // Parallel fold by warp 0 while all data loads are in flight.
    if (w == 0) {
        int i = l & 3;
        float g  = __ldg(gamma + i);
        float b  = __ldg(beta + i);
        float w0 = __ldg(W + i * 3 + 0);
        float d1 = __ldg(W + i * 3 + 1) - w0;
        float d2 = __ldg(W + i * 3 + 2) - w0;
        float B0 = g * d1, B1 = g * d2;
        float C0 = b * d1, C1 = b * d2;

        // width-4 butterfly: sums over i within each 4-lane group
        float s0 = B0, s1 = B1, c0 = C0, c1 = C1;
        s0 += __shfl_xor_sync(0xFFFFFFFFu, s0, 1, 4);
        s1 += __shfl_xor_sync(0xFFFFFFFFu, s1, 1, 4);
        c0 += __shfl_xor_sync(0xFFFFFFFFu, c0, 1, 4);
        c1 += __shfl_xor_sync(0xFFFFFFFFu, c1, 1, 4);
        s0 += __shfl_xor_sync(0xFFFFFFFFu, s0, 2, 4);
        s1 += __shfl_xor_sync(0xFFFFFFFFu, s1, 2, 4);
        c0 += __shfl_xor_sync(0xFFFFFFFFu, c0, 2, 4);
        c1 += __shfl_xor_sync(0xFFFFFFFFu, c1, 2, 4);

        if (l < 4) {
            sp[i]     = B0 - s0 * 0.25f;   // column-mean-centered B'
            sp[4 + i] = B1 - s1 * 0.25f;
        }
        if (l == 0) {
            sp[8] = __expf(c0);
            sp[9] = __expf(c1);
        }
    }
    __syncthreads();

    float E0 = sp[8];
    float E1 = sp[9];
    uint32_t spAddr = (uint32_t)__cvta_generic_to_shared(sp);

    // Per-warp staging region: 128 rows * 3 floats = 1536B.
    float* sw = s + w * 384;

    #pragma unroll
    for (int r = 0; r < 4; r++) {
        float4 v = vs[r];

        float sum = (v.x + v.y) + (v.z + v.w);
        float mu  = sum * 0.25f;
        float sq  = fmaf(v.x, v.x, fmaf(v.y, v.y, fmaf(v.z, v.z, v.w * v.w)));
        float var = fmaf(sq, 0.25f, -mu * mu);
        float inv = rsqrtf(var + 1e-5f);

        // 2 broadcast LDS.128 per iteration, not hoistable into regs.
        float4 P = lds128_volatile(spAddr);
        float4 Q = lds128_volatile(spAddr + 16u);

        float d0 = fmaf(v.x, P.x, fmaf(v.y, P.y, fmaf(v.z, P.z, v.w * P.w)));
        float d1 = fmaf(v.x, Q.x, fmaf(v.y, Q.y, fmaf(v.z, Q.z, v.w * Q.w)));

        float e0 = E0 * __expf(inv * d0);
        float e1 = E1 * __expf(inv * d1);
        float rs = __fdividef(1.0f, 1.0f + e0 + e1);

        int rr = r * 32 + l;           // row within this warp's 128-row chunk
        sw[rr * 3 + 0] = rs;           // stride-3: coprime with 32 banks
        sw[rr * 3 + 1] = e0 * rs;
        sw[rr * 3 + 2] = e1 * rs;
    }

    __syncwarp();   // warp-local staging visibility; no block barrier

    // Flush this warp's 96 float4 (1536B), coalesced 512B STG.128 requests.
    float4* ob = out4 + (size_t)blockIdx.x * (ROWS_PER_BLOCK * 3 / 4) + w * 96;
    const float4* s4 = (const float4*)sw;
    ob[l]      = s4[l];
    ob[l + 32] = s4[l + 32];
    ob[l + 64] = s4[l + 64];
}

extern "C" void kernel_launch(void* const* d_in, const int* in_sizes, int n_in,
                              void* d_out, int out_size)
{
    const float* x     = (const float*)d_in[0];   // [N,4]
    const float* W     = (const float*)d_in[1];   // [4,3]
    const float* gamma = (const float*)d_in[2];   // [4]
    const float* beta  = (const float*)d_in[3];   // [4]
    float* out = (float*)d_out;                   // [N,3]

    int n_rows = in_sizes[0] / 4;
    int blocks = n_rows / ROWS_PER_BLOCK;         // 8192, exact
    lnsm_kernel<<<blocks, 256>>>((const float4*)x, W, gamma, beta, (float4*)out);
}